// round 8
// baseline (speedup 1.0000x reference)
#include <cuda_runtime.h>
#include <cstddef>

// Fixed problem shape: bs=32, V=65536, F=130050, C=6.  BS == warp size.
#define BS 32
#define NV 65536
#define NF 130050
#define NC 6

#define QSCALE 32766.0f
#define QINV   (1.0f / 32766.0f)

// Scratch (device globals), batch-innermost:
//   g_pts4[v*32+b] = (x,y,z,0) fp32   : 33.6 MB  (1 LDG.128 per vertex-gather)
//   g_fn4 [f*32+b] = (x,y,z,0) snorm16: 33.3 MB  (1 LDG.64  per face-gather)
__device__ float4 g_pts4[(size_t)NV * BS];
__device__ short4 g_fn4[(size_t)NF * BS];

// ---------------------------------------------------------------------------
// Kernel 1: transpose points (BS,3,V) -> g_pts4[v*32+b].
// 64-vertex tile, 256 threads (R6 config: no forced occupancy).
// ---------------------------------------------------------------------------
#define TV 64
__global__ void __launch_bounds__(256)
transpose_kernel(const float* __restrict__ points)
{
    __shared__ float s[3][TV][33];          // [c][v_in_tile][b], 25.3 KB
    int v0 = blockIdx.x * TV;
    int t  = threadIdx.x;

    // Phase 1: 96 rows (b*3+c) x 16 float4 = 1536 vector loads; 6 per thread.
#pragma unroll
    for (int k = 0; k < 6; k++) {
        int idx  = t + k * 256;             // 0..1535
        int row  = idx >> 4;                // 0..95 = b*3 + c
        int col4 = idx & 15;
        int b    = row / 3;
        int c    = row - 3 * b;
        float4 p = *(const float4*)&points[(size_t)row * NV + v0 + col4 * 4];
        int vj = col4 * 4;
        s[c][vj + 0][b] = p.x;
        s[c][vj + 1][b] = p.y;
        s[c][vj + 2][b] = p.z;
        s[c][vj + 3][b] = p.w;
    }
    __syncthreads();

    // Phase 2: 8 warps x 8 rows; 3 conflict-free LDS + 1 STG.128 per iter.
    int lane = t & 31;
    int wid  = t >> 5;
#pragma unroll
    for (int r = wid; r < TV; r += 8) {
        float4 o = make_float4(s[0][r][lane], s[1][r][lane], s[2][r][lane], 0.0f);
        g_pts4[(size_t)(v0 + r) * BS + lane] = o;
    }
}

// ---------------------------------------------------------------------------
// Kernel 2: face normals.  warp = 4 faces, lane = batch.  MLP = 12 gathers.
// ---------------------------------------------------------------------------
__global__ void __launch_bounds__(256)
face_normals_kernel(const int* __restrict__ faces)
{
    int w    = (blockIdx.x * 256 + threadIdx.x) >> 5;  // warp id
    int lane = threadIdx.x & 31;                       // = batch
    int f0   = 4 * w;
    if (f0 >= NF) return;
    int nfaces = (NF - f0 < 4) ? (NF - f0) : 4;

    // 12 face-vertex indices for 4 faces.
    int idx[12];
    if (nfaces == 4) {
        const int4* fr = (const int4*)(faces + 3 * f0);  // 48B, 16B-aligned
        int4 a = __ldg(&fr[0]);
        int4 b = __ldg(&fr[1]);
        int4 c = __ldg(&fr[2]);
        idx[0] = a.x;  idx[1]  = a.y;  idx[2]  = a.z;  idx[3]  = a.w;
        idx[4] = b.x;  idx[5]  = b.y;  idx[6]  = b.z;  idx[7]  = b.w;
        idx[8] = c.x;  idx[9]  = c.y;  idx[10] = c.z;  idx[11] = c.w;
    } else {
#pragma unroll
        for (int k = 0; k < 12; k++)
            idx[k] = (k < 3 * nfaces) ? faces[3 * f0 + k] : 0;
    }

    // Issue all 12 gathers up front (independent).
    float4 P[12];
#pragma unroll
    for (int k = 0; k < 12; k++)
        if (k < 3 * nfaces)
            P[k] = g_pts4[(size_t)idx[k] * BS + lane];

#pragma unroll
    for (int j = 0; j < 4; j++) {
        if (j < nfaces) {
            float4 p0 = P[3 * j + 0];
            float4 p1 = P[3 * j + 1];
            float4 p2 = P[3 * j + 2];
            float ax = p1.x - p0.x, ay = p1.y - p0.y, az = p1.z - p0.z;
            float bx = p2.x - p0.x, by = p2.y - p0.y, bz = p2.z - p0.z;
            float cx = ay * bz - az * by;
            float cy = az * bx - ax * bz;
            float cz = ax * by - ay * bx;
            float inv = QSCALE * rsqrtf(fmaxf(cx*cx + cy*cy + cz*cz, 1e-24f));
            g_fn4[(size_t)(f0 + j) * BS + lane] =
                make_short4((short)__float2int_rn(cx * inv),
                            (short)__float2int_rn(cy * inv),
                            (short)__float2int_rn(cz * inv), 0);
        }
    }
}

// ---------------------------------------------------------------------------
// Kernel 3: vertex normals.  warp = 2 vertices, lane = batch.  MLP = 12.
// ---------------------------------------------------------------------------
__global__ void __launch_bounds__(256)
vertex_normals_kernel(const int*   __restrict__ vti,   // (V, C)
                      const float* __restrict__ vtw,   // (V, C)
                      float*       __restrict__ out)   // (BS, V, 3)
{
    __shared__ float so[16][33][3];         // [v_in_block][b][xyz]

    int wid  = threadIdx.x >> 5;            // 0..7
    int lane = threadIdx.x & 31;            // = batch
    int bv0  = blockIdx.x * 16;             // block's first vertex
    int v    = bv0 + wid * 2;               // this warp: v, v+1

    int   f[2 * NC];
    float wgt[2 * NC];
#pragma unroll
    for (int h = 0; h < 2; h++) {
        const int2*   vti2 = (const int2*)(vti + (v + h) * NC);
        const float2* vtw2 = (const float2*)(vtw + (v + h) * NC);
#pragma unroll
        for (int c = 0; c < 3; c++) {
            int2   fi = __ldg(&vti2[c]);
            float2 wi = __ldg(&vtw2[c]);
            f[h * NC + 2 * c + 0]   = fi.x;
            f[h * NC + 2 * c + 1]   = fi.y;
            wgt[h * NC + 2 * c + 0] = wi.x * QINV;
            wgt[h * NC + 2 * c + 1] = wi.y * QINV;
        }
    }

    // 12 independent gathers.
    short4 n[2 * NC];
#pragma unroll
    for (int c = 0; c < 2 * NC; c++)
        n[c] = g_fn4[(size_t)f[c] * BS + lane];

#pragma unroll
    for (int h = 0; h < 2; h++) {
        float ax = 0.0f, ay = 0.0f, az = 0.0f;
#pragma unroll
        for (int c = 0; c < NC; c++) {
            int i = h * NC + c;
            ax = fmaf((float)n[i].x, wgt[i], ax);
            ay = fmaf((float)n[i].y, wgt[i], ay);
            az = fmaf((float)n[i].z, wgt[i], az);
        }
        float inv = rsqrtf(fmaxf(ax*ax + ay*ay + az*az, 1e-24f));
        so[wid * 2 + h][lane][0] = ax * inv;
        so[wid * 2 + h][lane][1] = ay * inv;
        so[wid * 2 + h][lane][2] = az * inv;
    }
    __syncthreads();

    // Write out (b, v, 3): 2 rounds of 8 vertices; 12B contiguous per thread.
    int b = threadIdx.x >> 3;
    int j = threadIdx.x & 7;
#pragma unroll
    for (int h = 0; h < 2; h++) {
        size_t o = ((size_t)b * NV + (bv0 + h * 8 + j)) * 3;
        out[o + 0] = so[h * 8 + j][b][0];
        out[o + 1] = so[h * 8 + j][b][1];
        out[o + 2] = so[h * 8 + j][b][2];
    }
}

// ---------------------------------------------------------------------------
extern "C" void kernel_launch(void* const* d_in, const int* in_sizes, int n_in,
                              void* d_out, int out_size)
{
    const float* points = (const float*)d_in[0];  // (BS, 3, V)
    const int*   faces  = (const int*)  d_in[1];  // (F, 3)
    const int*   vti    = (const int*)  d_in[2];  // (V, C)
    const float* vtw    = (const float*)d_in[3];  // (V, C, 1)
    float*       out    = (float*)d_out;          // (BS, V, 3)

    transpose_kernel<<<NV / TV, 256>>>(points);

    {
        int warps  = (NF + 3) / 4;          // 32513
        int blocks = (warps + 7) / 8;       // 8 warps per block
        face_normals_kernel<<<blocks, 256>>>(faces);
    }

    vertex_normals_kernel<<<NV / 16, 256>>>(vti, vtw, out);
}

// round 9
// speedup vs baseline: 1.0740x; 1.0740x over previous
#include <cuda_runtime.h>
#include <cstddef>

// Fixed problem shape: bs=32, V=65536, F=130050, C=6.  BS == warp size.
#define BS 32
#define NV 65536
#define NF 130050
#define NC 6

#define QSCALE 32766.0f
#define QINV   (1.0f / 32766.0f)

// Scratch (device globals), batch-innermost:
//   g_pts4[v*32+b] = (x,y,z,0) fp32   : 33.6 MB  (1 LDG.128 per vertex-gather)
//   g_fn4 [f*32+b] = (x,y,z,0) snorm16: 33.3 MB  (1 LDG.64  per face-gather)
__device__ float4 g_pts4[(size_t)NV * BS];
__device__ short4 g_fn4[(size_t)NF * BS];

// ---------------------------------------------------------------------------
// Kernel 1: transpose points (BS,3,V) -> g_pts4[v*32+b].
// ---------------------------------------------------------------------------
#define TV 64
__global__ void __launch_bounds__(256)
transpose_kernel(const float* __restrict__ points)
{
    __shared__ float s[3][TV][33];          // [c][v_in_tile][b], 25.3 KB
    int v0 = blockIdx.x * TV;
    int t  = threadIdx.x;

    // Phase 1: 96 rows (b*3+c) x 16 float4 = 1536 vector loads; 6 per thread.
#pragma unroll
    for (int k = 0; k < 6; k++) {
        int idx  = t + k * 256;             // 0..1535
        int row  = idx >> 4;                // 0..95 = b*3 + c
        int col4 = idx & 15;
        int b    = row / 3;
        int c    = row - 3 * b;
        float4 p = *(const float4*)&points[(size_t)row * NV + v0 + col4 * 4];
        int vj = col4 * 4;
        s[c][vj + 0][b] = p.x;
        s[c][vj + 1][b] = p.y;
        s[c][vj + 2][b] = p.z;
        s[c][vj + 3][b] = p.w;
    }
    __syncthreads();

    // Phase 2: 8 warps x 8 rows; 3 conflict-free LDS + 1 STG.128 per iter.
    int lane = t & 31;
    int wid  = t >> 5;
#pragma unroll
    for (int r = wid; r < TV; r += 8) {
        float4 o = make_float4(s[0][r][lane], s[1][r][lane], s[2][r][lane], 0.0f);
        g_pts4[(size_t)(v0 + r) * BS + lane] = o;
    }

#if __CUDA_ARCH__ >= 900
    cudaTriggerProgrammaticLaunchCompletion();
#endif
}

// ---------------------------------------------------------------------------
// Kernel 2: face normals.  warp = 2 faces, lane = batch.  MLP = 6 gathers.
// PDL: index loads before grid-dependency sync.
// ---------------------------------------------------------------------------
__global__ void __launch_bounds__(256)
face_normals_kernel(const int* __restrict__ faces)
{
    int w    = (blockIdx.x * 256 + threadIdx.x) >> 5;  // warp id
    int lane = threadIdx.x & 31;                       // = batch
    int f0   = 2 * w;
    bool act = (f0 < NF);                              // NF even -> f0+1 valid

    // Prologue (independent of K1): 6 indices via 3x int2.
    int2 ia = make_int2(0, 0), ib = ia, ic = ia;
    if (act) {
        const int2* fr = (const int2*)(faces + 3 * f0);
        ia = __ldg(&fr[0]);
        ib = __ldg(&fr[1]);
        ic = __ldg(&fr[2]);
    }

#if __CUDA_ARCH__ >= 900
    cudaGridDependencySynchronize();
#endif
    if (!act) return;

    // Issue all 6 gathers up front (independent).
    float4 p0 = g_pts4[(size_t)ia.x * BS + lane];
    float4 p1 = g_pts4[(size_t)ia.y * BS + lane];
    float4 p2 = g_pts4[(size_t)ib.x * BS + lane];
    float4 q0 = g_pts4[(size_t)ib.y * BS + lane];
    float4 q1 = g_pts4[(size_t)ic.x * BS + lane];
    float4 q2 = g_pts4[(size_t)ic.y * BS + lane];

    {
        float ax = p1.x - p0.x, ay = p1.y - p0.y, az = p1.z - p0.z;
        float bx = p2.x - p0.x, by = p2.y - p0.y, bz = p2.z - p0.z;
        float cx = ay * bz - az * by;
        float cy = az * bx - ax * bz;
        float cz = ax * by - ay * bx;
        float inv = QSCALE * rsqrtf(fmaxf(cx*cx + cy*cy + cz*cz, 1e-24f));
        g_fn4[(size_t)f0 * BS + lane] =
            make_short4((short)__float2int_rn(cx * inv),
                        (short)__float2int_rn(cy * inv),
                        (short)__float2int_rn(cz * inv), 0);
    }
    {
        float ax = q1.x - q0.x, ay = q1.y - q0.y, az = q1.z - q0.z;
        float bx = q2.x - q0.x, by = q2.y - q0.y, bz = q2.z - q0.z;
        float cx = ay * bz - az * by;
        float cy = az * bx - ax * bz;
        float cz = ax * by - ay * bx;
        float inv = QSCALE * rsqrtf(fmaxf(cx*cx + cy*cy + cz*cz, 1e-24f));
        g_fn4[(size_t)(f0 + 1) * BS + lane] =
            make_short4((short)__float2int_rn(cx * inv),
                        (short)__float2int_rn(cy * inv),
                        (short)__float2int_rn(cz * inv), 0);
    }

#if __CUDA_ARCH__ >= 900
    cudaTriggerProgrammaticLaunchCompletion();
#endif
}

// ---------------------------------------------------------------------------
// Kernel 3: vertex normals.  warp = 2 vertices, lane = batch.  MLP = 12.
// PDL: vti/vtw loads before grid-dependency sync.
// ---------------------------------------------------------------------------
__global__ void __launch_bounds__(256)
vertex_normals_kernel(const int*   __restrict__ vti,   // (V, C)
                      const float* __restrict__ vtw,   // (V, C)
                      float*       __restrict__ out)   // (BS, V, 3)
{
    __shared__ float so[16][33][3];         // [v_in_block][b][xyz]

    int wid  = threadIdx.x >> 5;            // 0..7
    int lane = threadIdx.x & 31;            // = batch
    int bv0  = blockIdx.x * 16;             // block's first vertex
    int v    = bv0 + wid * 2;               // this warp: v, v+1

    // Prologue (independent of K2): uniform index/weight loads.
    int   f[2 * NC];
    float wgt[2 * NC];
#pragma unroll
    for (int h = 0; h < 2; h++) {
        const int2*   vti2 = (const int2*)(vti + (v + h) * NC);
        const float2* vtw2 = (const float2*)(vtw + (v + h) * NC);
#pragma unroll
        for (int c = 0; c < 3; c++) {
            int2   fi = __ldg(&vti2[c]);
            float2 wi = __ldg(&vtw2[c]);
            f[h * NC + 2 * c + 0]   = fi.x;
            f[h * NC + 2 * c + 1]   = fi.y;
            wgt[h * NC + 2 * c + 0] = wi.x * QINV;
            wgt[h * NC + 2 * c + 1] = wi.y * QINV;
        }
    }

#if __CUDA_ARCH__ >= 900
    cudaGridDependencySynchronize();
#endif

    // 12 independent gathers.
    short4 n[2 * NC];
#pragma unroll
    for (int c = 0; c < 2 * NC; c++)
        n[c] = g_fn4[(size_t)f[c] * BS + lane];

#pragma unroll
    for (int h = 0; h < 2; h++) {
        float ax = 0.0f, ay = 0.0f, az = 0.0f;
#pragma unroll
        for (int c = 0; c < NC; c++) {
            int i = h * NC + c;
            ax = fmaf((float)n[i].x, wgt[i], ax);
            ay = fmaf((float)n[i].y, wgt[i], ay);
            az = fmaf((float)n[i].z, wgt[i], az);
        }
        float inv = rsqrtf(fmaxf(ax*ax + ay*ay + az*az, 1e-24f));
        so[wid * 2 + h][lane][0] = ax * inv;
        so[wid * 2 + h][lane][1] = ay * inv;
        so[wid * 2 + h][lane][2] = az * inv;
    }
    __syncthreads();

    // Write out (b, v, 3): 2 rounds of 8 vertices; 12B contiguous per thread.
    int b = threadIdx.x >> 3;
    int j = threadIdx.x & 7;
#pragma unroll
    for (int h = 0; h < 2; h++) {
        size_t o = ((size_t)b * NV + (bv0 + h * 8 + j)) * 3;
        out[o + 0] = so[h * 8 + j][b][0];
        out[o + 1] = so[h * 8 + j][b][1];
        out[o + 2] = so[h * 8 + j][b][2];
    }
}

// ---------------------------------------------------------------------------
extern "C" void kernel_launch(void* const* d_in, const int* in_sizes, int n_in,
                              void* d_out, int out_size)
{
    const float* points = (const float*)d_in[0];  // (BS, 3, V)
    const int*   faces  = (const int*)  d_in[1];  // (F, 3)
    const int*   vti    = (const int*)  d_in[2];  // (V, C)
    const float* vtw    = (const float*)d_in[3];  // (V, C, 1)
    float*       out    = (float*)d_out;          // (BS, V, 3)

    // K1: normal launch.
    transpose_kernel<<<NV / TV, 256>>>(points);

    // K2, K3: programmatic dependent launches (PDL) — overlap prologue with
    // the producer's tail.  Captured as PDL edges in the CUDA graph.
    cudaLaunchAttribute attr[1];
    attr[0].id = cudaLaunchAttributeProgrammaticStreamSerialization;
    attr[0].val.programmaticStreamSerializationAllowed = 1;

    {
        int warps  = NF / 2;                // 65025
        int blocks = (warps + 7) / 8;       // 8 warps per block
        cudaLaunchConfig_t cfg = {};
        cfg.gridDim  = dim3(blocks);
        cfg.blockDim = dim3(256);
        cfg.attrs    = attr;
        cfg.numAttrs = 1;
        cudaLaunchKernelEx(&cfg, face_normals_kernel, faces);
    }
    {
        cudaLaunchConfig_t cfg = {};
        cfg.gridDim  = dim3(NV / 16);
        cfg.blockDim = dim3(256);
        cfg.attrs    = attr;
        cfg.numAttrs = 1;
        cudaLaunchKernelEx(&cfg, vertex_normals_kernel, vti, vtw, out);
    }
}

// round 11
// speedup vs baseline: 1.0778x; 1.0035x over previous
#include <cuda_runtime.h>
#include <cstddef>

// Fixed problem shape: bs=32, V=65536, F=130050, C=6.  BS == warp size.
#define BS 32
#define NV 65536
#define NF 130050
#define NC 6

#define QSCALE 32766.0f            // fn snorm16 encode
#define QINV   (1.0f / 32766.0f)

// Scratch (device globals), batch-innermost:
//   g_ptsXY[v*32+b] = (x,y) fp32    : 16.8 MB (1 LDG.64 per vertex-gather)
//   g_ptsZ [v*32+b] = z fp32        :  8.4 MB (1 LDG.32 per vertex-gather)
//   g_fn4  [f*32+b] = (x,y,z,0) s16 : 33.3 MB (1 LDG.64 per face-gather)
__device__ float2 g_ptsXY[(size_t)NV * BS];
__device__ float  g_ptsZ[(size_t)NV * BS];
__device__ short4 g_fn4[(size_t)NF * BS];

// ---------------------------------------------------------------------------
// Kernel 1: transpose points (BS,3,V) -> split planes.
// 64-vertex tile, 256 threads, float4 global loads.
// ---------------------------------------------------------------------------
#define TV 64
__global__ void __launch_bounds__(256)
transpose_kernel(const float* __restrict__ points)
{
    __shared__ float s[3][TV][33];          // [c][v_in_tile][b], 25.3 KB
    int v0 = blockIdx.x * TV;
    int t  = threadIdx.x;

    // Phase 1: 96 rows (b*3+c) x 16 float4 = 1536 vector loads; 6 per thread.
#pragma unroll
    for (int k = 0; k < 6; k++) {
        int idx  = t + k * 256;             // 0..1535
        int row  = idx >> 4;                // 0..95 = b*3 + c
        int col4 = idx & 15;
        int b    = row / 3;
        int c    = row - 3 * b;
        float4 p = *(const float4*)&points[(size_t)row * NV + v0 + col4 * 4];
        int vj = col4 * 4;
        s[c][vj + 0][b] = p.x;
        s[c][vj + 1][b] = p.y;
        s[c][vj + 2][b] = p.z;
        s[c][vj + 3][b] = p.w;
    }
    __syncthreads();

    // Phase 2: 8 warps x 8 rows; conflict-free LDS; 1 STG.64 + 1 STG.32.
    int lane = t & 31;
    int wid  = t >> 5;
#pragma unroll
    for (int r = wid; r < TV; r += 8) {
        size_t o = (size_t)(v0 + r) * BS + lane;
        g_ptsXY[o] = make_float2(s[0][r][lane], s[1][r][lane]);
        g_ptsZ[o]  = s[2][r][lane];
    }

#if __CUDA_ARCH__ >= 900
    cudaTriggerProgrammaticLaunchCompletion();
#endif
}

// ---------------------------------------------------------------------------
// Kernel 2: face normals.  warp = 2 faces, lane = batch.  12 gathers (MLP=12).
// ---------------------------------------------------------------------------
__global__ void __launch_bounds__(256)
face_normals_kernel(const int* __restrict__ faces)
{
    int w    = (blockIdx.x * 256 + threadIdx.x) >> 5;  // warp id
    int lane = threadIdx.x & 31;                       // = batch
    int f0   = 2 * w;
    bool act = (f0 < NF);                              // NF even -> f0+1 valid

    // Prologue (independent of K1): 6 indices via 3x int2.
    int2 ia = make_int2(0, 0), ib = ia, ic = ia;
    if (act) {
        const int2* fr = (const int2*)(faces + 3 * f0);
        ia = __ldg(&fr[0]);
        ib = __ldg(&fr[1]);
        ic = __ldg(&fr[2]);
    }

#if __CUDA_ARCH__ >= 900
    cudaGridDependencySynchronize();
#endif
    if (!act) return;

    size_t o0 = (size_t)ia.x * BS + lane;
    size_t o1 = (size_t)ia.y * BS + lane;
    size_t o2 = (size_t)ib.x * BS + lane;
    size_t o3 = (size_t)ib.y * BS + lane;
    size_t o4 = (size_t)ic.x * BS + lane;
    size_t o5 = (size_t)ic.y * BS + lane;

    // Issue all 12 gathers up front (independent).
    float2 u0 = g_ptsXY[o0];  float z0 = g_ptsZ[o0];
    float2 u1 = g_ptsXY[o1];  float z1 = g_ptsZ[o1];
    float2 u2 = g_ptsXY[o2];  float z2 = g_ptsZ[o2];
    float2 u3 = g_ptsXY[o3];  float z3 = g_ptsZ[o3];
    float2 u4 = g_ptsXY[o4];  float z4 = g_ptsZ[o4];
    float2 u5 = g_ptsXY[o5];  float z5 = g_ptsZ[o5];

    // Face f0: verts (u0,z0),(u1,z1),(u2,z2)
    {
        float ax = u1.x - u0.x, ay = u1.y - u0.y, az = z1 - z0;
        float bx = u2.x - u0.x, by = u2.y - u0.y, bz = z2 - z0;
        float cx = ay * bz - az * by;
        float cy = az * bx - ax * bz;
        float cz = ax * by - ay * bx;
        float inv = QSCALE * rsqrtf(fmaxf(cx*cx + cy*cy + cz*cz, 1e-24f));
        g_fn4[(size_t)f0 * BS + lane] =
            make_short4((short)__float2int_rn(cx * inv),
                        (short)__float2int_rn(cy * inv),
                        (short)__float2int_rn(cz * inv), 0);
    }
    // Face f0+1: verts (u3,z3),(u4,z4),(u5,z5)
    {
        float ax = u4.x - u3.x, ay = u4.y - u3.y, az = z4 - z3;
        float bx = u5.x - u3.x, by = u5.y - u3.y, bz = z5 - z3;
        float cx = ay * bz - az * by;
        float cy = az * bx - ax * bz;
        float cz = ax * by - ay * bx;
        float inv = QSCALE * rsqrtf(fmaxf(cx*cx + cy*cy + cz*cz, 1e-24f));
        g_fn4[(size_t)(f0 + 1) * BS + lane] =
            make_short4((short)__float2int_rn(cx * inv),
                        (short)__float2int_rn(cy * inv),
                        (short)__float2int_rn(cz * inv), 0);
    }

#if __CUDA_ARCH__ >= 900
    cudaTriggerProgrammaticLaunchCompletion();
#endif
}

// ---------------------------------------------------------------------------
// Kernel 3: vertex normals.  warp = 2 vertices, lane = batch.  MLP = 12.
// ---------------------------------------------------------------------------
__global__ void __launch_bounds__(256)
vertex_normals_kernel(const int*   __restrict__ vti,   // (V, C)
                      const float* __restrict__ vtw,   // (V, C)
                      float*       __restrict__ out)   // (BS, V, 3)
{
    __shared__ float so[16][33][3];         // [v_in_block][b][xyz]

    int wid  = threadIdx.x >> 5;            // 0..7
    int lane = threadIdx.x & 31;            // = batch
    int bv0  = blockIdx.x * 16;             // block's first vertex
    int v    = bv0 + wid * 2;               // this warp: v, v+1

    // Prologue (independent of K2): uniform index/weight loads.
    int   f[2 * NC];
    float wgt[2 * NC];
#pragma unroll
    for (int h = 0; h < 2; h++) {
        const int2*   vti2 = (const int2*)(vti + (v + h) * NC);
        const float2* vtw2 = (const float2*)(vtw + (v + h) * NC);
#pragma unroll
        for (int c = 0; c < 3; c++) {
            int2   fi = __ldg(&vti2[c]);
            float2 wi = __ldg(&vtw2[c]);
            f[h * NC + 2 * c + 0]   = fi.x;
            f[h * NC + 2 * c + 1]   = fi.y;
            wgt[h * NC + 2 * c + 0] = wi.x * QINV;
            wgt[h * NC + 2 * c + 1] = wi.y * QINV;
        }
    }

#if __CUDA_ARCH__ >= 900
    cudaGridDependencySynchronize();
#endif

    // 12 independent gathers.
    short4 n[2 * NC];
#pragma unroll
    for (int c = 0; c < 2 * NC; c++)
        n[c] = g_fn4[(size_t)f[c] * BS + lane];

#pragma unroll
    for (int h = 0; h < 2; h++) {
        float ax = 0.0f, ay = 0.0f, az = 0.0f;
#pragma unroll
        for (int c = 0; c < NC; c++) {
            int i = h * NC + c;
            ax = fmaf((float)n[i].x, wgt[i], ax);
            ay = fmaf((float)n[i].y, wgt[i], ay);
            az = fmaf((float)n[i].z, wgt[i], az);
        }
        float inv = rsqrtf(fmaxf(ax*ax + ay*ay + az*az, 1e-24f));
        so[wid * 2 + h][lane][0] = ax * inv;
        so[wid * 2 + h][lane][1] = ay * inv;
        so[wid * 2 + h][lane][2] = az * inv;
    }
    __syncthreads();

    // Write out (b, v, 3): 2 rounds of 8 vertices; 12B contiguous per thread.
    int b = threadIdx.x >> 3;
    int j = threadIdx.x & 7;
#pragma unroll
    for (int h = 0; h < 2; h++) {
        size_t o = ((size_t)b * NV + (bv0 + h * 8 + j)) * 3;
        out[o + 0] = so[h * 8 + j][b][0];
        out[o + 1] = so[h * 8 + j][b][1];
        out[o + 2] = so[h * 8 + j][b][2];
    }
}

// ---------------------------------------------------------------------------
extern "C" void kernel_launch(void* const* d_in, const int* in_sizes, int n_in,
                              void* d_out, int out_size)
{
    const float* points = (const float*)d_in[0];  // (BS, 3, V)
    const int*   faces  = (const int*)  d_in[1];  // (F, 3)
    const int*   vti    = (const int*)  d_in[2];  // (V, C)
    const float* vtw    = (const float*)d_in[3];  // (V, C, 1)
    float*       out    = (float*)d_out;          // (BS, V, 3)

    // K1: normal launch.
    transpose_kernel<<<NV / TV, 256>>>(points);

    // K2, K3: programmatic dependent launches (PDL).
    cudaLaunchAttribute attr[1];
    attr[0].id = cudaLaunchAttributeProgrammaticStreamSerialization;
    attr[0].val.programmaticStreamSerializationAllowed = 1;

    {
        int warps  = NF / 2;                // 65025
        int blocks = (warps + 7) / 8;       // 8 warps per block
        cudaLaunchConfig_t cfg = {};
        cfg.gridDim  = dim3(blocks);
        cfg.blockDim = dim3(256);
        cfg.attrs    = attr;
        cfg.numAttrs = 1;
        cudaLaunchKernelEx(&cfg, face_normals_kernel, faces);
    }
    {
        cudaLaunchConfig_t cfg = {};
        cfg.gridDim  = dim3(NV / 16);
        cfg.blockDim = dim3(256);
        cfg.attrs    = attr;
        cfg.numAttrs = 1;
        cudaLaunchKernelEx(&cfg, vertex_normals_kernel, vti, vtw, out);
    }
}